// round 7
// baseline (speedup 1.0000x reference)
#include <cuda_runtime.h>

#define RR 256
#define TT 32
#define BB 32
#define YSZ 64

#define TILE 64
#define XS 68      // x tile with halo 2 on each side
#define HS 66      // conv1 output tile (halo 1 for conv2)
#define HSTR 68    // padded stride for 16B-aligned float4 loads

// 8MB scratch for stage-1 output (device global: no allocation)
__device__ float g_x[BB * RR * RR];

// ---------------------------------------------------------------------------
// Stage 1: x[b,p,q] = sum_t Ht[t,p,q] * yt[b,t,p>>2,q>>2]
// Grid: (256 rows p, 8 batch-groups of 4). 256 threads = q.
// ---------------------------------------------------------------------------
__global__ __launch_bounds__(256) void stage1_kernel(
    const float* __restrict__ yt, const float* __restrict__ Ht)
{
    __shared__ float s_yt[4][TT][YSZ];   // 32 KB

    const int p   = blockIdx.x;
    const int bg  = blockIdx.y;          // group of 4 batches
    const int tid = threadIdx.x;
    const int yr  = p >> 2;

    // Load yt slices for 4 batches, all t, this row group: coalesced
    for (int i = tid; i < 4 * TT * YSZ; i += 256) {
        int q4 = i & 63;
        int t  = (i >> 6) & 31;
        int bl = i >> 11;
        s_yt[bl][t][q4] = yt[(((bg * 4 + bl) * TT + t) * YSZ + yr) * YSZ + q4];
    }
    __syncthreads();

    const int q  = tid;
    const int q4 = q >> 2;
    const float* hp = Ht + p * RR + q;

    float a0 = 0.f, a1 = 0.f, a2 = 0.f, a3 = 0.f;
#pragma unroll
    for (int t = 0; t < TT; t++) {
        float h = hp[t * RR * RR];
        a0 = fmaf(h, s_yt[0][t][q4], a0);
        a1 = fmaf(h, s_yt[1][t][q4], a1);
        a2 = fmaf(h, s_yt[2][t][q4], a2);
        a3 = fmaf(h, s_yt[3][t][q4], a3);
    }
    float* xp = g_x + (bg * 4) * RR * RR + p * RR + q;
    xp[0 * RR * RR] = a0;
    xp[1 * RR * RR] = a1;
    xp[2 * RR * RR] = a2;
    xp[3 * RR * RR] = a3;
}

// ---------------------------------------------------------------------------
// Stage 2+3 fused: Conv(1->32,3x3,SAME) -> ReLU -> Conv(32->1,3x3,SAME)
// One CTA computes a 64x64 output tile for one batch. Channels streamed
// through a single shared h-tile; 4x4 register tile per thread.
// Grid: (4, 4, 32 batches). 256 threads (16x16).
// ---------------------------------------------------------------------------
__global__ __launch_bounds__(256) void conv_fused_kernel(
    const float* __restrict__ W1, const float* __restrict__ b1,
    const float* __restrict__ W2, const float* __restrict__ b2,
    float* __restrict__ out)
{
    __shared__ __align__(16) float xs[XS * XS];     // 18.5 KB
    __shared__ __align__(16) float hs[HS * HSTR];   // 17.95 KB
    __shared__ float w1s[32 * 9];
    __shared__ float w2s[32 * 9];
    __shared__ float b1s[32];
    __shared__ float b2s;

    const int b   = blockIdx.z;
    const int ty0 = blockIdx.y * TILE;
    const int tx0 = blockIdx.x * TILE;
    const int tid = threadIdx.x;

    // 288 weights > 256 threads — strided loop (R2 fix).
    for (int i = tid; i < 288; i += 256) { w1s[i] = W1[i]; w2s[i] = W2[i]; }
    if (tid < 32)  b1s[tid] = b1[tid];
    if (tid == 0)  b2s = b2[0];

    // Load x tile with halo 2 (zero-pad at image borders)
    const float* xb = g_x + b * RR * RR;
    for (int i = tid; i < XS * XS; i += 256) {
        int ry = i / XS, rx = i - ry * XS;
        int gy = ty0 - 2 + ry, gx = tx0 - 2 + rx;
        float v = 0.f;
        if (gy >= 0 && gy < RR && gx >= 0 && gx < RR) v = xb[gy * RR + gx];
        xs[i] = v;
    }
    __syncthreads();

    const int tx = tid & 15;
    const int ty = tid >> 4;
    const int ox = tx * 4;      // output col within tile
    const int oy = ty * 4;      // output row within tile

    float acc[4][4];
#pragma unroll
    for (int i = 0; i < 4; i++)
#pragma unroll
        for (int j = 0; j < 4; j++) acc[i][j] = 0.f;

    for (int c = 0; c < 32; c++) {
        // --- conv1 for channel c: 66x66 points, ReLU, into hs ---
        float w[9];
#pragma unroll
        for (int k = 0; k < 9; k++) w[k] = w1s[c * 9 + k];
        float bc = b1s[c];

#pragma unroll
        for (int it = 0; it < 18; it++) {
            int idx = tid + it * 256;
            if (idx < HS * HS) {
                int hy = idx / HS, hx = idx - hy * HS;
                const float* xp = xs + hy * XS + hx;
                float v = bc;
                v = fmaf(w[0], xp[0], v);
                v = fmaf(w[1], xp[1], v);
                v = fmaf(w[2], xp[2], v);
                v = fmaf(w[3], xp[XS + 0], v);
                v = fmaf(w[4], xp[XS + 1], v);
                v = fmaf(w[5], xp[XS + 2], v);
                v = fmaf(w[6], xp[2 * XS + 0], v);
                v = fmaf(w[7], xp[2 * XS + 1], v);
                v = fmaf(w[8], xp[2 * XS + 2], v);
                float r = fmaxf(v, 0.f);
                // FIX (R5): conv2's SAME padding zero-pads the conv1 OUTPUT
                // outside the image. Halo positions beyond the image border
                // must be 0, not conv1 applied to the zero-padded input.
                int gyh = ty0 + hy - 1;
                int gxh = tx0 + hx - 1;
                if ((unsigned)gyh >= RR || (unsigned)gxh >= RR) r = 0.f;
                hs[hy * HSTR + hx] = r;
            }
        }
        __syncthreads();

        // --- conv2 accumulate channel c into 4x4 register tile ---
        float w2r[9];
#pragma unroll
        for (int k = 0; k < 9; k++) w2r[k] = w2s[c * 9 + k];

#pragma unroll
        for (int pr = 0; pr < 6; pr++) {
            const float* hp = hs + (oy + pr) * HSTR + ox;
            float4 v4 = *(const float4*)hp;        // 16B aligned (HSTR%4==0, ox%4==0)
            float2 v2 = *(const float2*)(hp + 4);
            float rv[6] = { v4.x, v4.y, v4.z, v4.w, v2.x, v2.y };
#pragma unroll
            for (int i = 0; i < 4; i++) {
                int dy = pr - i;
                if (dy >= 0 && dy < 3) {
#pragma unroll
                    for (int j = 0; j < 4; j++) {
                        acc[i][j] = fmaf(w2r[dy * 3 + 0], rv[j],     acc[i][j]);
                        acc[i][j] = fmaf(w2r[dy * 3 + 1], rv[j + 1], acc[i][j]);
                        acc[i][j] = fmaf(w2r[dy * 3 + 2], rv[j + 2], acc[i][j]);
                    }
                }
            }
        }
        __syncthreads();   // protect hs before next channel overwrites it
    }

    // Epilogue: add b2, store coalesced float4
    float bb = b2s;
#pragma unroll
    for (int i = 0; i < 4; i++) {
        float4 o;
        o.x = acc[i][0] + bb;
        o.y = acc[i][1] + bb;
        o.z = acc[i][2] + bb;
        o.w = acc[i][3] + bb;
        *(float4*)(out + (size_t)(b * RR + ty0 + oy + i) * RR + tx0 + ox) = o;
    }
}

extern "C" void kernel_launch(void* const* d_in, const int* in_sizes, int n_in,
                              void* d_out, int out_size) {
    const float* yt = (const float*)d_in[0];
    const float* Ht = (const float*)d_in[1];
    const float* W1 = (const float*)d_in[2];
    const float* b1 = (const float*)d_in[3];
    const float* W2 = (const float*)d_in[4];
    const float* b2 = (const float*)d_in[5];
    float* out = (float*)d_out;

    stage1_kernel<<<dim3(256, 8), 256>>>(yt, Ht);
    conv_fused_kernel<<<dim3(4, 4, 32), 256>>>(W1, b1, W2, b2, out);
}

// round 8
// speedup vs baseline: 1.7746x; 1.7746x over previous
#include <cuda_runtime.h>

#define RR 256
#define TT 32
#define BB 32
#define YSZ 64

#define TILE 64
#define XS 68      // x tile with halo 2 on each side
#define HS 66      // conv1 output tile (halo 1 for conv2)
#define HSTR 68    // padded stride for 16B-aligned float4 loads
#define CH 4       // channels per hs pass

#define XS_FLOATS   (XS * XS)          // 4624
#define HS_FLOATS   (HS * HSTR)        // 4488
#define SMEM_FLOATS (XS_FLOATS + CH * HS_FLOATS + 288 + 288 + 32 + 1)
#define SMEM_BYTES  (SMEM_FLOATS * 4)  // 92740

// 8MB scratch for stage-1 output (device global: no allocation)
__device__ float g_x[BB * RR * RR];

// ---------------------------------------------------------------------------
// Stage 1: x[b,p,q] = sum_t Ht[t,p,q] * yt[b,t,p>>2,q>>2]
// ---------------------------------------------------------------------------
__global__ __launch_bounds__(256) void stage1_kernel(
    const float* __restrict__ yt, const float* __restrict__ Ht)
{
    __shared__ float s_yt[4][TT][YSZ];   // 32 KB

    const int p   = blockIdx.x;
    const int bg  = blockIdx.y;
    const int tid = threadIdx.x;
    const int yr  = p >> 2;

    for (int i = tid; i < 4 * TT * YSZ; i += 256) {
        int q4 = i & 63;
        int t  = (i >> 6) & 31;
        int bl = i >> 11;
        s_yt[bl][t][q4] = yt[(((bg * 4 + bl) * TT + t) * YSZ + yr) * YSZ + q4];
    }
    __syncthreads();

    const int q  = tid;
    const int q4 = q >> 2;
    const float* hp = Ht + p * RR + q;

    float a0 = 0.f, a1 = 0.f, a2 = 0.f, a3 = 0.f;
#pragma unroll
    for (int t = 0; t < TT; t++) {
        float h = hp[t * RR * RR];
        a0 = fmaf(h, s_yt[0][t][q4], a0);
        a1 = fmaf(h, s_yt[1][t][q4], a1);
        a2 = fmaf(h, s_yt[2][t][q4], a2);
        a3 = fmaf(h, s_yt[3][t][q4], a3);
    }
    float* xp = g_x + (bg * 4) * RR * RR + p * RR + q;
    xp[0 * RR * RR] = a0;
    xp[1 * RR * RR] = a1;
    xp[2 * RR * RR] = a2;
    xp[3 * RR * RR] = a3;
}

// ---------------------------------------------------------------------------
// Conv(1->32,3x3) -> ReLU -> Conv(32->1,3x3), fused, CH=4 channels per pass.
// Grid: (4, 4, 32). 256 threads. Dynamic smem: xs + 4x hs + weights.
// ---------------------------------------------------------------------------
__global__ __launch_bounds__(256, 2) void conv_fused_kernel(
    const float* __restrict__ W1, const float* __restrict__ b1,
    const float* __restrict__ W2, const float* __restrict__ b2,
    float* __restrict__ out)
{
    extern __shared__ float smem[];
    float* xs  = smem;                        // 68x68
    float* hsb = smem + XS_FLOATS;            // CH * 66x68
    float* w1s = hsb + CH * HS_FLOATS;        // 288
    float* w2s = w1s + 288;                   // 288
    float* b1s = w2s + 288;                   // 32
    float* b2s = b1s + 32;                    // 1

    const int b   = blockIdx.z;
    const int ty0 = blockIdx.y * TILE;
    const int tx0 = blockIdx.x * TILE;
    const int tid = threadIdx.x;

    for (int i = tid; i < 288; i += 256) { w1s[i] = W1[i]; w2s[i] = W2[i]; }
    if (tid < 32)  b1s[tid] = b1[tid];
    if (tid == 0)  b2s[0] = b2[0];

    // Load x tile with halo 2 (zero-pad at image borders)
    const float* xb = g_x + b * RR * RR;
    for (int i = tid; i < XS_FLOATS; i += 256) {
        int ry = i / XS, rx = i - ry * XS;
        int gy = ty0 - 2 + ry, gx = tx0 - 2 + rx;
        float v = 0.f;
        if (gy >= 0 && gy < RR && gx >= 0 && gx < RR) v = xb[gy * RR + gx];
        xs[i] = v;
    }
    __syncthreads();

    const int tx = tid & 15;
    const int ty = tid >> 4;
    const int ox = tx * 4;
    const int oy = ty * 4;

    // channel-invariant starting point for the conv1 point walk
    const int hy0 = tid / HS;
    const int hx0 = tid - hy0 * HS;

    float acc[4][4];
#pragma unroll
    for (int i = 0; i < 4; i++)
#pragma unroll
        for (int j = 0; j < 4; j++) acc[i][j] = 0.f;

    for (int g = 0; g < 32 / CH; g++) {
        const int c0 = g * CH;

        // stage weights for this channel group into registers
        float w1r[CH][9], bcr[CH];
#pragma unroll
        for (int cc = 0; cc < CH; cc++) {
#pragma unroll
            for (int k = 0; k < 9; k++) w1r[cc][k] = w1s[(c0 + cc) * 9 + k];
            bcr[cc] = b1s[c0 + cc];
        }

        // --- conv1: 66x66 points, CH channels per x-load ---
        {
            int hy = hy0, hx = hx0;
#pragma unroll 6
            for (int it = 0; it < 17; it++) {
                const float* xp = xs + hy * XS + hx;
                float x0 = xp[0],          x1 = xp[1],          x2 = xp[2];
                float x3 = xp[XS + 0],     x4 = xp[XS + 1],     x5 = xp[XS + 2];
                float x6 = xp[2 * XS + 0], x7 = xp[2 * XS + 1], x8 = xp[2 * XS + 2];
                int gyh = ty0 + hy - 1;
                int gxh = tx0 + hx - 1;
                bool oob = ((unsigned)gyh >= RR) || ((unsigned)gxh >= RR);
                float* hp = hsb + hy * HSTR + hx;
#pragma unroll
                for (int cc = 0; cc < CH; cc++) {
                    float v = bcr[cc];
                    v = fmaf(w1r[cc][0], x0, v);
                    v = fmaf(w1r[cc][1], x1, v);
                    v = fmaf(w1r[cc][2], x2, v);
                    v = fmaf(w1r[cc][3], x3, v);
                    v = fmaf(w1r[cc][4], x4, v);
                    v = fmaf(w1r[cc][5], x5, v);
                    v = fmaf(w1r[cc][6], x6, v);
                    v = fmaf(w1r[cc][7], x7, v);
                    v = fmaf(w1r[cc][8], x8, v);
                    float r = fmaxf(v, 0.f);
                    if (oob) r = 0.f;
                    hp[cc * HS_FLOATS] = r;
                }
                // advance by 256 points: 256 = 3*66 + 58
                hx += 58; hy += 3;
                if (hx >= HS) { hx -= HS; hy += 1; }
            }
            // tail: 4356 - 17*256 = 4 points
            if (tid < 4) {
                const float* xp = xs + hy * XS + hx;
                float x0 = xp[0],          x1 = xp[1],          x2 = xp[2];
                float x3 = xp[XS + 0],     x4 = xp[XS + 1],     x5 = xp[XS + 2];
                float x6 = xp[2 * XS + 0], x7 = xp[2 * XS + 1], x8 = xp[2 * XS + 2];
                int gyh = ty0 + hy - 1;
                int gxh = tx0 + hx - 1;
                bool oob = ((unsigned)gyh >= RR) || ((unsigned)gxh >= RR);
                float* hp = hsb + hy * HSTR + hx;
#pragma unroll
                for (int cc = 0; cc < CH; cc++) {
                    float v = bcr[cc];
                    v = fmaf(w1r[cc][0], x0, v);
                    v = fmaf(w1r[cc][1], x1, v);
                    v = fmaf(w1r[cc][2], x2, v);
                    v = fmaf(w1r[cc][3], x3, v);
                    v = fmaf(w1r[cc][4], x4, v);
                    v = fmaf(w1r[cc][5], x5, v);
                    v = fmaf(w1r[cc][6], x6, v);
                    v = fmaf(w1r[cc][7], x7, v);
                    v = fmaf(w1r[cc][8], x8, v);
                    float r = fmaxf(v, 0.f);
                    if (oob) r = 0.f;
                    hp[cc * HS_FLOATS] = r;
                }
            }
        }
        __syncthreads();

        // --- conv2: accumulate CH channels into 4x4 register tile ---
#pragma unroll
        for (int cc = 0; cc < CH; cc++) {
            float w2r[9];
#pragma unroll
            for (int k = 0; k < 9; k++) w2r[k] = w2s[(c0 + cc) * 9 + k];
            const float* hc = hsb + cc * HS_FLOATS;
#pragma unroll
            for (int pr = 0; pr < 6; pr++) {
                const float* hp = hc + (oy + pr) * HSTR + ox;
                float4 v4 = *(const float4*)hp;
                float2 v2 = *(const float2*)(hp + 4);
                float rv[6] = { v4.x, v4.y, v4.z, v4.w, v2.x, v2.y };
#pragma unroll
                for (int i = 0; i < 4; i++) {
                    int dy = pr - i;
                    if (dy >= 0 && dy < 3) {
#pragma unroll
                        for (int j = 0; j < 4; j++) {
                            acc[i][j] = fmaf(w2r[dy * 3 + 0], rv[j],     acc[i][j]);
                            acc[i][j] = fmaf(w2r[dy * 3 + 1], rv[j + 1], acc[i][j]);
                            acc[i][j] = fmaf(w2r[dy * 3 + 2], rv[j + 2], acc[i][j]);
                        }
                    }
                }
            }
        }
        __syncthreads();   // protect hs before next group overwrites it
    }

    float bb = b2s[0];
#pragma unroll
    for (int i = 0; i < 4; i++) {
        float4 o;
        o.x = acc[i][0] + bb;
        o.y = acc[i][1] + bb;
        o.z = acc[i][2] + bb;
        o.w = acc[i][3] + bb;
        *(float4*)(out + (size_t)(b * RR + ty0 + oy + i) * RR + tx0 + ox) = o;
    }
}

extern "C" void kernel_launch(void* const* d_in, const int* in_sizes, int n_in,
                              void* d_out, int out_size) {
    const float* yt = (const float*)d_in[0];
    const float* Ht = (const float*)d_in[1];
    const float* W1 = (const float*)d_in[2];
    const float* b1 = (const float*)d_in[3];
    const float* W2 = (const float*)d_in[4];
    const float* b2 = (const float*)d_in[5];
    float* out = (float*)d_out;

    // Immediate (non-stream) API: executes at call time, not captured.
    cudaFuncSetAttribute(conv_fused_kernel,
                         cudaFuncAttributeMaxDynamicSharedMemorySize, SMEM_BYTES);

    stage1_kernel<<<dim3(256, 8), 256>>>(yt, Ht);
    conv_fused_kernel<<<dim3(4, 4, 32), 256, SMEM_BYTES>>>(W1, b1, W2, b2, out);
}